// round 5
// baseline (speedup 1.0000x reference)
#include <cuda_runtime.h>
#include <cuda_bf16.h>
#include <cstdint>

// FourierCrossAttention: B=64, L=S=2048, H=8, E=64, MODES=64, O=64
// out[b,h,o,l] = irfft_l( scatter( w-contraction( tanh(Xq^T Xk) Xk ) ) ) / (512*512)

#define N_B   64
#define N_L   2048
#define N_H   8
#define N_E   64
#define N_M   64
#define N_HE  512
#define N_J   128   // 2*N_M, interleaved (re,im)

typedef unsigned long long ull;

// ---------- scratch (static device globals; no runtime alloc) ----------------
__device__ float g_Bf[N_L * N_J];          // forward basis [l][j]
__device__ float g_Bi[N_J * N_L];          // inverse basis [j][l] (coef folded)
__device__ float g_Xq[N_B * N_HE * N_J];
__device__ float g_Xk[N_B * N_HE * N_J];
__device__ float g_Spec[N_B * N_HE * N_J];

// ---------- packed f32x2 helpers ---------------------------------------------
__device__ __forceinline__ ull pk2(float lo, float hi) {
    ull r; asm("mov.b64 %0, {%1, %2};" : "=l"(r) : "f"(lo), "f"(hi)); return r;
}
__device__ __forceinline__ void fma2(ull &d, ull a, ull b) {
    asm("fma.rn.f32x2 %0, %1, %2, %0;" : "+l"(d) : "l"(a), "l"(b));
}
__device__ __forceinline__ void add2(ull &d, ull a) {
    asm("add.rn.f32x2 %0, %0, %1;" : "+l"(d) : "l"(a));
}

// ---------- K0: basis tables -------------------------------------------------
__global__ void k_basis() {
    int idx = blockIdx.x * blockDim.x + threadIdx.x;   // 64*2048 threads
    int m = idx >> 11;
    int l = idx & 2047;
    int rr = (m * l) & 2047;
    double th = (double)rr * (6.283185307179586476925287 / 2048.0);
    double s, cd;
    sincos(th, &s, &cd);
    g_Bf[l * N_J + 2 * m]     = (float)cd;
    g_Bf[l * N_J + 2 * m + 1] = (float)(-s);
    double coef = (m == 0 ? 1.0 : 2.0) / (2048.0 * 512.0 * 512.0);
    g_Bi[(2 * m) * N_L + l]     = (float)(coef * cd);
    g_Bi[(2 * m + 1) * N_L + l] = (m == 0) ? 0.0f : (float)(-coef * s);
}

// ---------- K1: truncated DFT as GEMM, K=2048, chunked accumulation ----------
// grid (8 he-tiles, 64 b, 2 {q,k}); 256 thr; tile 64he x 128j; thread 4x8.
__global__ void __launch_bounds__(256, 2) k_dft(const float* __restrict__ qp,
                                                const float* __restrict__ kp) {
    const float* src = blockIdx.z ? kp : qp;
    float* dst       = blockIdx.z ? g_Xk : g_Xq;
    int b = blockIdx.y;
    int he0 = blockIdx.x * 64;

    __shared__ __align__(16) float sA[32][64];
    __shared__ __align__(16) float sB[32][128];

    int t = threadIdx.x;
    int r = t >> 4, c = t & 15;
    int hs = r * 4, js = c * 8;

    ull acc[4][4], accM[4][4];
#pragma unroll
    for (int i = 0; i < 4; i++)
#pragma unroll
        for (int q = 0; q < 4; q++) { acc[i][q] = 0ull; accM[i][q] = 0ull; }

    const float* abase = src + (size_t)b * N_L * N_HE + he0;
    int rowL = t >> 3;
    int ca = (t & 7) * 8;
    int cb = (t & 7) * 16;

    for (int l0 = 0; l0 < N_L; l0 += 32) {
        const float* g = abase + (size_t)(l0 + rowL) * N_HE + ca;
        *(float4*)&sA[rowL][ca]     = *(const float4*)g;
        *(float4*)&sA[rowL][ca + 4] = *(const float4*)(g + 4);
        const float* gb = g_Bf + (size_t)(l0 + rowL) * N_J + cb;
        *(float4*)&sB[rowL][cb]      = *(const float4*)gb;
        *(float4*)&sB[rowL][cb + 4]  = *(const float4*)(gb + 4);
        *(float4*)&sB[rowL][cb + 8]  = *(const float4*)(gb + 8);
        *(float4*)&sB[rowL][cb + 12] = *(const float4*)(gb + 12);
        __syncthreads();
#pragma unroll
        for (int kk = 0; kk < 32; kk++) {
            float4 a4 = *(float4*)&sA[kk][hs];
            ull aa[4];
            aa[0] = pk2(a4.x, a4.x); aa[1] = pk2(a4.y, a4.y);
            aa[2] = pk2(a4.z, a4.z); aa[3] = pk2(a4.w, a4.w);
            ulonglong2 b0 = *(ulonglong2*)&sB[kk][js];
            ulonglong2 b1 = *(ulonglong2*)&sB[kk][js + 4];
            ull bb[4] = {b0.x, b0.y, b1.x, b1.y};
#pragma unroll
            for (int i = 0; i < 4; i++) {
                fma2(acc[i][0], aa[i], bb[0]);
                fma2(acc[i][1], aa[i], bb[1]);
                fma2(acc[i][2], aa[i], bb[2]);
                fma2(acc[i][3], aa[i], bb[3]);
            }
        }
        __syncthreads();
        if (((l0 >> 5) & 7) == 7) {   // flush every 256 l's: tames fp32 drift
#pragma unroll
            for (int i = 0; i < 4; i++)
#pragma unroll
                for (int q = 0; q < 4; q++) { add2(accM[i][q], acc[i][q]); acc[i][q] = 0ull; }
        }
    }
#pragma unroll
    for (int i = 0; i < 4; i++) {
        float* dp = dst + (size_t)(b * N_HE + he0 + hs + i) * N_J + js;
        ulonglong2 s0, s1;
        s0.x = accM[i][0]; s0.y = accM[i][1];
        s1.x = accM[i][2]; s1.y = accM[i][3];
        *(ulonglong2*)dp = s0;
        *((ulonglong2*)dp + 1) = s1;
    }
}

// ---------- complex tanh (stable; double internally) -------------------------
__device__ __forceinline__ float2 ctanh_c(float re, float im) {
    double tx = tanh((double)re);
    double ty = tan((double)im);
    double tx2 = tx * tx, ty2 = ty * ty;
    double inv = 1.0 / (1.0 + tx2 * ty2);
    return make_float2((float)(tx * (1.0 + ty2) * inv),
                       (float)(ty * (1.0 - tx2) * inv));
}

// ---------- K2: fused middle stage, one block per (b,h) ----------------------
#define K2_SMEM (3 * 64 * 66 * (int)sizeof(float2))
__global__ void __launch_bounds__(256, 2) k_mid(const float* __restrict__ w1r,
                                                const float* __restrict__ w1i) {
    int bh = blockIdx.x;
    int b = bh >> 3, h = bh & 7;
    extern __shared__ float2 sm2[];
    float2 (*sQ)[66] = (float2(*)[66])sm2;          // Xq[e][x] -> later Xqkv
    float2 (*sK)[66] = ((float2(*)[66])sm2) + 64;   // Xk[e][y]
    float2 (*sA)[66] = ((float2(*)[66])sm2) + 128;  // A[y][x]

    int t = threadIdx.x;
    int r = t >> 4, c = t & 15;
    int xs = c * 4;

    const float* xqb = g_Xq + (size_t)(b * N_HE + h * N_E) * N_J;
    const float* xkb = g_Xk + (size_t)(b * N_HE + h * N_E) * N_J;
    for (int i = t; i < 64 * 32; i += 256) {
        int row = i >> 5, c4 = i & 31;
        *(float4*)&sQ[row][c4 * 2] = *(const float4*)(xqb + row * N_J + c4 * 4);
        *(float4*)&sK[row][c4 * 2] = *(const float4*)(xkb + row * N_J + c4 * 4);
    }
    __syncthreads();

    // stage A: A[x][y] = tanh( sum_e Xq[e][x]*Xk[e][y] )   (no conjugate)
    {
        int ys = r * 4;
        float are[4][4] = {}, aim[4][4] = {};
        for (int e = 0; e < 64; e++) {
            float4 q0 = *(float4*)&sQ[e][xs];
            float4 q1 = *(float4*)&sQ[e][xs + 2];
            float qr[4] = {q0.x, q0.z, q1.x, q1.z};
            float qi[4] = {q0.y, q0.w, q1.y, q1.w};
            float4 k0 = *(float4*)&sK[e][ys];
            float4 k1 = *(float4*)&sK[e][ys + 2];
            float kr[4] = {k0.x, k0.z, k1.x, k1.z};
            float ki[4] = {k0.y, k0.w, k1.y, k1.w};
#pragma unroll
            for (int i = 0; i < 4; i++)
#pragma unroll
                for (int j = 0; j < 4; j++) {
                    are[i][j] = fmaf(qr[i], kr[j], are[i][j]);
                    are[i][j] = fmaf(-qi[i], ki[j], are[i][j]);
                    aim[i][j] = fmaf(qr[i], ki[j], aim[i][j]);
                    aim[i][j] = fmaf(qi[i], kr[j], aim[i][j]);
                }
        }
#pragma unroll
        for (int i = 0; i < 4; i++)
#pragma unroll
            for (int j = 0; j < 4; j++)
                sA[ys + j][xs + i] = ctanh_c(are[i][j], aim[i][j]);
    }
    __syncthreads();

    // stage B: Xqkv[e][x] = sum_y A[x][y]*Xk[e][y]   -> overwrite sQ
    {
        int es = r * 4;
        float vre[4][4] = {}, vim[4][4] = {};   // [e][x]
        for (int y = 0; y < 64; y++) {
            float4 a0 = *(float4*)&sA[y][xs];
            float4 a1 = *(float4*)&sA[y][xs + 2];
            float ar[4] = {a0.x, a0.z, a1.x, a1.z};
            float ai[4] = {a0.y, a0.w, a1.y, a1.w};
            float2 kv[4];
#pragma unroll
            for (int j = 0; j < 4; j++) kv[j] = sK[es + j][y];
#pragma unroll
            for (int ei = 0; ei < 4; ei++)
#pragma unroll
                for (int xi = 0; xi < 4; xi++) {
                    vre[ei][xi] = fmaf(ar[xi], kv[ei].x, vre[ei][xi]);
                    vre[ei][xi] = fmaf(-ai[xi], kv[ei].y, vre[ei][xi]);
                    vim[ei][xi] = fmaf(ar[xi], kv[ei].y, vim[ei][xi]);
                    vim[ei][xi] = fmaf(ai[xi], kv[ei].x, vim[ei][xi]);
                }
        }
        __syncthreads();   // everyone done reading old sQ? (sQ unread in B, but A read it)
#pragma unroll
        for (int ei = 0; ei < 4; ei++)
#pragma unroll
            for (int xi = 0; xi < 4; xi++)
                sQ[es + ei][xs + xi] = make_float2(vre[ei][xi], vim[ei][xi]);
    }
    __syncthreads();

    // stage C: Spec[o][x] = sum_e Xqkv[e][x] * w[h,e,o,x]
    {
        int os = r * 4;
        float sre[4][4] = {}, sim_[4][4] = {};  // [o][x]
        for (int e = 0; e < 64; e++) {
            float4 x0 = *(float4*)&sQ[e][xs];
            float4 x1 = *(float4*)&sQ[e][xs + 2];
            float xr[4] = {x0.x, x0.z, x1.x, x1.z};
            float xi_[4] = {x0.y, x0.w, x1.y, x1.w};
            size_t wo = (((size_t)h * 64 + e) * 64 + os) * 64 + xs;
#pragma unroll
            for (int j = 0; j < 4; j++) {
                float4 w4r = *(const float4*)(w1r + wo + (size_t)j * 64);
                float4 w4i = *(const float4*)(w1i + wo + (size_t)j * 64);
                float wr[4] = {w4r.x, w4r.y, w4r.z, w4r.w};
                float wi[4] = {w4i.x, w4i.y, w4i.z, w4i.w};
#pragma unroll
                for (int i = 0; i < 4; i++) {
                    sre[j][i]  = fmaf(xr[i],  wr[i], sre[j][i]);
                    sre[j][i]  = fmaf(-xi_[i], wi[i], sre[j][i]);
                    sim_[j][i] = fmaf(xr[i],  wi[i], sim_[j][i]);
                    sim_[j][i] = fmaf(xi_[i], wr[i], sim_[j][i]);
                }
            }
        }
        float* sp = g_Spec + (size_t)(b * N_HE + h * N_E) * N_J;
#pragma unroll
        for (int j = 0; j < 4; j++)
#pragma unroll
            for (int i = 0; i < 4; i++)
                *(float2*)&sp[(os + j) * N_J + 2 * (xs + i)] =
                    make_float2(sre[j][i], sim_[j][i]);
    }
}

// ---------- K3: irfft as GEMM, K=128 -----------------------------------------
// grid (16 l-tiles, 512 row-tiles); 256 thr; tile 64row x 128l; thread 4x8.
__global__ void __launch_bounds__(256, 2) k_irfft(float* __restrict__ out) {
    int r0 = blockIdx.y * 64;
    int l0 = blockIdx.x * 128;

    __shared__ __align__(16) float sS[64][32];
    __shared__ __align__(16) float sB[32][128];

    int t = threadIdx.x;
    int r = t >> 4, c = t & 15;
    int hs = r * 4, js = c * 8;

    ull acc[4][4];
#pragma unroll
    for (int i = 0; i < 4; i++)
#pragma unroll
        for (int q = 0; q < 4; q++) acc[i][q] = 0ull;

    int rowS = t >> 2;            // 0..63
    int caS = (t & 3) * 8;        // 0..24
    int rowJ = t >> 3;            // 0..31
    int cb = (t & 7) * 16;

    for (int j0 = 0; j0 < N_J; j0 += 32) {
        const float* gs = g_Spec + (size_t)(r0 + rowS) * N_J + j0 + caS;
        *(float4*)&sS[rowS][caS]     = *(const float4*)gs;
        *(float4*)&sS[rowS][caS + 4] = *(const float4*)(gs + 4);
        const float* gb = g_Bi + (size_t)(j0 + rowJ) * N_L + l0 + cb;
        *(float4*)&sB[rowJ][cb]      = *(const float4*)gb;
        *(float4*)&sB[rowJ][cb + 4]  = *(const float4*)(gb + 4);
        *(float4*)&sB[rowJ][cb + 8]  = *(const float4*)(gb + 8);
        *(float4*)&sB[rowJ][cb + 12] = *(const float4*)(gb + 12);
        __syncthreads();
#pragma unroll
        for (int kk = 0; kk < 32; kk++) {
            float4 a4 = *(float4*)&sS[hs][0 + kk];   // placeholder; fixed below
            (void)a4;
            break;
        }
        // real inner loop (sS is [row][j]; per kk read 4 rows' scalar)
#pragma unroll
        for (int kk = 0; kk < 32; kk++) {
            ull aa[4];
            aa[0] = pk2(sS[hs + 0][kk], sS[hs + 0][kk]);
            aa[1] = pk2(sS[hs + 1][kk], sS[hs + 1][kk]);
            aa[2] = pk2(sS[hs + 2][kk], sS[hs + 2][kk]);
            aa[3] = pk2(sS[hs + 3][kk], sS[hs + 3][kk]);
            ulonglong2 b0 = *(ulonglong2*)&sB[kk][js];
            ulonglong2 b1 = *(ulonglong2*)&sB[kk][js + 4];
            ull bb[4] = {b0.x, b0.y, b1.x, b1.y};
#pragma unroll
            for (int i = 0; i < 4; i++) {
                fma2(acc[i][0], aa[i], bb[0]);
                fma2(acc[i][1], aa[i], bb[1]);
                fma2(acc[i][2], aa[i], bb[2]);
                fma2(acc[i][3], aa[i], bb[3]);
            }
        }
        __syncthreads();
    }
#pragma unroll
    for (int i = 0; i < 4; i++) {
        float* dp = out + (size_t)(r0 + hs + i) * N_L + l0 + js;
        ulonglong2 s0, s1;
        s0.x = acc[i][0]; s0.y = acc[i][1];
        s1.x = acc[i][2]; s1.y = acc[i][3];
        *(ulonglong2*)dp = s0;
        *((ulonglong2*)dp + 1) = s1;
    }
}

// ---------- launch ------------------------------------------------------------
extern "C" void kernel_launch(void* const* d_in, const int* in_sizes, int n_in,
                              void* d_out, int out_size) {
    const float* q   = (const float*)d_in[0];
    const float* k   = (const float*)d_in[1];
    const float* w1r = (const float*)d_in[3];
    const float* w1i = (const float*)d_in[4];
    float* out = (float*)d_out;

    cudaFuncSetAttribute(k_mid, cudaFuncAttributeMaxDynamicSharedMemorySize, K2_SMEM);

    k_basis<<<512, 256>>>();
    dim3 g1(8, 64, 2);
    k_dft<<<g1, 256>>>(q, k);
    k_mid<<<512, 256, K2_SMEM>>>(w1r, w1i);
    dim3 g3(16, 512);
    k_irfft<<<g3, 256>>>(out);
}

// round 6
// speedup vs baseline: 1.4746x; 1.4746x over previous
#include <cuda_runtime.h>
#include <cuda_bf16.h>
#include <cstdint>

// FourierCrossAttention: B=64, L=S=2048, H=8, E=64, MODES=64, O=64
// out[b,h,o,l] = irfft_l( scatter( w-contraction( tanh(Xq^T Xk) Xk ) ) ) / (512*512)

#define N_B   64
#define N_L   2048
#define N_H   8
#define N_E   64
#define N_M   64
#define N_HE  512
#define N_J   128   // 2*N_M, interleaved (re,im)

typedef unsigned long long ull;

// ---------- scratch (static device globals; no runtime alloc) ----------------
__device__ float g_Bf[N_L * N_J];          // forward basis [l][j]
__device__ float g_Bi[N_J * N_L];          // inverse basis [j][l] (coef folded)
__device__ float g_Xq[N_B * N_HE * N_J];
__device__ float g_Xk[N_B * N_HE * N_J];
__device__ float g_Spec[N_B * N_HE * N_J];

// ---------- packed f32x2 helpers ---------------------------------------------
__device__ __forceinline__ ull pk2(float lo, float hi) {
    ull r; asm("mov.b64 %0, {%1, %2};" : "=l"(r) : "f"(lo), "f"(hi)); return r;
}
__device__ __forceinline__ void fma2(ull &d, ull a, ull b) {
    asm("fma.rn.f32x2 %0, %1, %2, %0;" : "+l"(d) : "l"(a), "l"(b));
}
__device__ __forceinline__ void add2(ull &d, ull a) {
    asm("add.rn.f32x2 %0, %0, %1;" : "+l"(d) : "l"(a));
}

// ---------- K0: basis tables -------------------------------------------------
__global__ void k_basis() {
    int idx = blockIdx.x * blockDim.x + threadIdx.x;   // 64*2048 threads
    int m = idx >> 11;
    int l = idx & 2047;
    int rr = (m * l) & 2047;
    double th = (double)rr * (6.283185307179586476925287 / 2048.0);
    double s, cd;
    sincos(th, &s, &cd);
    g_Bf[l * N_J + 2 * m]     = (float)cd;
    g_Bf[l * N_J + 2 * m + 1] = (float)(-s);
    double coef = (m == 0 ? 1.0 : 2.0) / (2048.0 * 512.0 * 512.0);
    g_Bi[(2 * m) * N_L + l]     = (float)(coef * cd);
    g_Bi[(2 * m + 1) * N_L + l] = (m == 0) ? 0.0f : (float)(-coef * s);
}

// ---------- K1: truncated DFT as GEMM, K=2048 --------------------------------
// grid (4 he-tiles, 64 b, 2 {q,k}); 128 thr; block tile 128he x 64 pairs (all j)
// thread tile: 8 he x 8 pairs (stride-8 pair assignment -> conflict-free LDS.64)
__global__ void __launch_bounds__(128) k_dft(const float* __restrict__ qp,
                                             const float* __restrict__ kp) {
    const float* src = blockIdx.z ? kp : qp;
    float* dst       = blockIdx.z ? g_Xk : g_Xq;
    int b = blockIdx.y;
    int he0 = blockIdx.x * 128;

    __shared__ __align__(16) float sA[32][128];   // [l][he]
    __shared__ __align__(16) float sB[32][128];   // [l][j]

    int t = threadIdx.x;
    int w = t >> 5, lane = t & 31;
    int tr = t >> 3, tc = t & 7;        // 16 x 8 thread grid
    int hs = tr * 8;                    // 8 he rows

    ull acc[8][8], accM[8][8];
#pragma unroll
    for (int i = 0; i < 8; i++)
#pragma unroll
        for (int q = 0; q < 8; q++) { acc[i][q] = 0ull; accM[i][q] = 0ull; }

    const float* abase = src + (size_t)b * N_L * N_HE + he0;

    for (int l0 = 0; l0 < N_L; l0 += 32) {
        // fill: each warp fills rows w, w+4, ..., w+28 ; one full row per step
#pragma unroll
        for (int rr = 0; rr < 8; rr++) {
            int row = w + rr * 4;
            *(float4*)&sA[row][lane * 4] =
                *(const float4*)(abase + (size_t)(l0 + row) * N_HE + lane * 4);
            *(float4*)&sB[row][lane * 4] =
                *(const float4*)(g_Bf + (size_t)(l0 + row) * N_J + lane * 4);
        }
        __syncthreads();
#pragma unroll 4
        for (int kk = 0; kk < 32; kk++) {
            float4 a0 = *(float4*)&sA[kk][hs];
            float4 a1 = *(float4*)&sA[kk][hs + 4];
            ull aa[8];
            aa[0] = pk2(a0.x, a0.x); aa[1] = pk2(a0.y, a0.y);
            aa[2] = pk2(a0.z, a0.z); aa[3] = pk2(a0.w, a0.w);
            aa[4] = pk2(a1.x, a1.x); aa[5] = pk2(a1.y, a1.y);
            aa[6] = pk2(a1.z, a1.z); aa[7] = pk2(a1.w, a1.w);
            ull bb[8];
#pragma unroll
            for (int i = 0; i < 8; i++)
                bb[i] = *(ull*)&sB[kk][2 * (tc + 8 * i)];
#pragma unroll
            for (int hi = 0; hi < 8; hi++)
#pragma unroll
                for (int i = 0; i < 8; i++)
                    fma2(acc[hi][i], aa[hi], bb[i]);
        }
        __syncthreads();
        if (((l0 >> 5) & 7) == 7) {   // flush every 256 l's: tames fp32 drift
#pragma unroll
            for (int i = 0; i < 8; i++)
#pragma unroll
                for (int q = 0; q < 8; q++) { add2(accM[i][q], acc[i][q]); acc[i][q] = 0ull; }
        }
    }
#pragma unroll
    for (int hi = 0; hi < 8; hi++) {
        float* dp = dst + (size_t)(b * N_HE + he0 + hs + hi) * N_J;
#pragma unroll
        for (int i = 0; i < 8; i++)
            *(ull*)&dp[2 * (tc + 8 * i)] = accM[hi][i];
    }
}

// ---------- complex tanh (stable; double internally) -------------------------
__device__ __forceinline__ float2 ctanh_c(float re, float im) {
    double tx = tanh((double)re);
    double ty = tan((double)im);
    double tx2 = tx * tx, ty2 = ty * ty;
    double inv = 1.0 / (1.0 + tx2 * ty2);
    return make_float2((float)(tx * (1.0 + ty2) * inv),
                       (float)(ty * (1.0 - tx2) * inv));
}

// ---------- K2: fused middle stage, one block per (b,h) ----------------------
#define K2_SMEM (3 * 64 * 66 * (int)sizeof(float2))
__global__ void __launch_bounds__(256, 2) k_mid(const float* __restrict__ w1r,
                                                const float* __restrict__ w1i) {
    int bh = blockIdx.x;
    int b = bh >> 3, h = bh & 7;
    extern __shared__ float2 sm2[];
    float2 (*sQ)[66] = (float2(*)[66])sm2;          // Xq[e][x] -> later Xqkv
    float2 (*sK)[66] = ((float2(*)[66])sm2) + 64;   // Xk[e][y]
    float2 (*sA)[66] = ((float2(*)[66])sm2) + 128;  // A[y][x]

    int t = threadIdx.x;
    int r = t >> 4, c = t & 15;
    int xs = c * 4;

    const float* xqb = g_Xq + (size_t)(b * N_HE + h * N_E) * N_J;
    const float* xkb = g_Xk + (size_t)(b * N_HE + h * N_E) * N_J;
    for (int i = t; i < 64 * 32; i += 256) {
        int row = i >> 5, c4 = i & 31;
        *(float4*)&sQ[row][c4 * 2] = *(const float4*)(xqb + row * N_J + c4 * 4);
        *(float4*)&sK[row][c4 * 2] = *(const float4*)(xkb + row * N_J + c4 * 4);
    }
    __syncthreads();

    // stage A: A[x][y] = tanh( sum_e Xq[e][x]*Xk[e][y] )   (no conjugate)
    {
        int ys = r * 4;
        float are[4][4] = {}, aim[4][4] = {};
        for (int e = 0; e < 64; e++) {
            float4 q0 = *(float4*)&sQ[e][xs];
            float4 q1 = *(float4*)&sQ[e][xs + 2];
            float qr[4] = {q0.x, q0.z, q1.x, q1.z};
            float qi[4] = {q0.y, q0.w, q1.y, q1.w};
            float4 k0 = *(float4*)&sK[e][ys];
            float4 k1 = *(float4*)&sK[e][ys + 2];
            float kr[4] = {k0.x, k0.z, k1.x, k1.z};
            float ki[4] = {k0.y, k0.w, k1.y, k1.w};
#pragma unroll
            for (int i = 0; i < 4; i++)
#pragma unroll
                for (int j = 0; j < 4; j++) {
                    are[i][j] = fmaf(qr[i], kr[j], are[i][j]);
                    are[i][j] = fmaf(-qi[i], ki[j], are[i][j]);
                    aim[i][j] = fmaf(qr[i], ki[j], aim[i][j]);
                    aim[i][j] = fmaf(qi[i], kr[j], aim[i][j]);
                }
        }
#pragma unroll
        for (int i = 0; i < 4; i++)
#pragma unroll
            for (int j = 0; j < 4; j++)
                sA[ys + j][xs + i] = ctanh_c(are[i][j], aim[i][j]);
    }
    __syncthreads();

    // stage B: Xqkv[e][x] = sum_y A[x][y]*Xk[e][y]   -> overwrite sQ
    {
        int es = r * 4;
        float vre[4][4] = {}, vim[4][4] = {};   // [e][x]
        for (int y = 0; y < 64; y++) {
            float4 a0 = *(float4*)&sA[y][xs];
            float4 a1 = *(float4*)&sA[y][xs + 2];
            float ar[4] = {a0.x, a0.z, a1.x, a1.z};
            float ai[4] = {a0.y, a0.w, a1.y, a1.w};
            float2 kv[4];
#pragma unroll
            for (int j = 0; j < 4; j++) kv[j] = sK[es + j][y];
#pragma unroll
            for (int ei = 0; ei < 4; ei++)
#pragma unroll
                for (int xi = 0; xi < 4; xi++) {
                    vre[ei][xi] = fmaf(ar[xi], kv[ei].x, vre[ei][xi]);
                    vre[ei][xi] = fmaf(-ai[xi], kv[ei].y, vre[ei][xi]);
                    vim[ei][xi] = fmaf(ar[xi], kv[ei].y, vim[ei][xi]);
                    vim[ei][xi] = fmaf(ai[xi], kv[ei].x, vim[ei][xi]);
                }
        }
        __syncthreads();
#pragma unroll
        for (int ei = 0; ei < 4; ei++)
#pragma unroll
            for (int xi = 0; xi < 4; xi++)
                sQ[es + ei][xs + xi] = make_float2(vre[ei][xi], vim[ei][xi]);
    }
    __syncthreads();

    // stage C: Spec[o][x] = sum_e Xqkv[e][x] * w[h,e,o,x]
    {
        int os = r * 4;
        float sre[4][4] = {}, sim_[4][4] = {};  // [o][x]
        for (int e = 0; e < 64; e++) {
            float4 x0 = *(float4*)&sQ[e][xs];
            float4 x1 = *(float4*)&sQ[e][xs + 2];
            float xr[4] = {x0.x, x0.z, x1.x, x1.z};
            float xi_[4] = {x0.y, x0.w, x1.y, x1.w};
            size_t wo = (((size_t)h * 64 + e) * 64 + os) * 64 + xs;
#pragma unroll
            for (int j = 0; j < 4; j++) {
                float4 w4r = *(const float4*)(w1r + wo + (size_t)j * 64);
                float4 w4i = *(const float4*)(w1i + wo + (size_t)j * 64);
                float wr[4] = {w4r.x, w4r.y, w4r.z, w4r.w};
                float wi[4] = {w4i.x, w4i.y, w4i.z, w4i.w};
#pragma unroll
                for (int i = 0; i < 4; i++) {
                    sre[j][i]  = fmaf(xr[i],  wr[i], sre[j][i]);
                    sre[j][i]  = fmaf(-xi_[i], wi[i], sre[j][i]);
                    sim_[j][i] = fmaf(xr[i],  wi[i], sim_[j][i]);
                    sim_[j][i] = fmaf(xi_[i], wr[i], sim_[j][i]);
                }
            }
        }
        float* sp = g_Spec + (size_t)(b * N_HE + h * N_E) * N_J;
#pragma unroll
        for (int j = 0; j < 4; j++)
#pragma unroll
            for (int i = 0; i < 4; i++)
                *(float2*)&sp[(os + j) * N_J + 2 * (xs + i)] =
                    make_float2(sre[j][i], sim_[j][i]);
    }
}

// ---------- K3: irfft as GEMM, K=128 -----------------------------------------
// grid (16 l-tiles, 256 row-tiles); 128 thr; block tile 128 rows x 128 l
// thread tile: 8 rows x 8 l-pairs (stride-8). Spec held transposed in smem.
__global__ void __launch_bounds__(128) k_irfft(float* __restrict__ out) {
    int l0 = blockIdx.x * 128;
    int r0 = blockIdx.y * 128;

    __shared__ __align__(16) float sST[32][128];   // [j][row]  (transposed)
    __shared__ __align__(16) float sB[32][128];    // [j][l]

    int t = threadIdx.x;
    int w = t >> 5, lane = t & 31;
    int tr = t >> 3, tc = t & 7;
    int hs = tr * 8;

    ull acc[8][8];
#pragma unroll
    for (int i = 0; i < 8; i++)
#pragma unroll
        for (int q = 0; q < 8; q++) acc[i][q] = 0ull;

    for (int j0 = 0; j0 < N_J; j0 += 32) {
        // Spec transpose fill: thread t owns Spec row r0+t; STS.32 bank = t%32 (clean)
        {
            const float* gs = g_Spec + (size_t)(r0 + t) * N_J + j0;
#pragma unroll
            for (int u = 0; u < 8; u++) {
                float4 v = *(const float4*)(gs + u * 4);
                sST[u * 4 + 0][t] = v.x;
                sST[u * 4 + 1][t] = v.y;
                sST[u * 4 + 2][t] = v.z;
                sST[u * 4 + 3][t] = v.w;
            }
        }
        // Bi fill: warp-per-row, coalesced
#pragma unroll
        for (int rr = 0; rr < 8; rr++) {
            int row = w + rr * 4;
            *(float4*)&sB[row][lane * 4] =
                *(const float4*)(g_Bi + (size_t)(j0 + row) * N_L + l0 + lane * 4);
        }
        __syncthreads();
#pragma unroll 4
        for (int kk = 0; kk < 32; kk++) {
            float4 a0 = *(float4*)&sST[kk][hs];
            float4 a1 = *(float4*)&sST[kk][hs + 4];
            ull aa[8];
            aa[0] = pk2(a0.x, a0.x); aa[1] = pk2(a0.y, a0.y);
            aa[2] = pk2(a0.z, a0.z); aa[3] = pk2(a0.w, a0.w);
            aa[4] = pk2(a1.x, a1.x); aa[5] = pk2(a1.y, a1.y);
            aa[6] = pk2(a1.z, a1.z); aa[7] = pk2(a1.w, a1.w);
            ull bb[8];
#pragma unroll
            for (int i = 0; i < 8; i++)
                bb[i] = *(ull*)&sB[kk][2 * (tc + 8 * i)];
#pragma unroll
            for (int hi = 0; hi < 8; hi++)
#pragma unroll
                for (int i = 0; i < 8; i++)
                    fma2(acc[hi][i], aa[hi], bb[i]);
        }
        __syncthreads();
    }
#pragma unroll
    for (int hi = 0; hi < 8; hi++) {
        float* dp = out + (size_t)(r0 + hs + hi) * N_L + l0;
#pragma unroll
        for (int i = 0; i < 8; i++)
            *(ull*)&dp[2 * (tc + 8 * i)] = acc[hi][i];
    }
}

// ---------- launch ------------------------------------------------------------
extern "C" void kernel_launch(void* const* d_in, const int* in_sizes, int n_in,
                              void* d_out, int out_size) {
    const float* q   = (const float*)d_in[0];
    const float* k   = (const float*)d_in[1];
    const float* w1r = (const float*)d_in[3];
    const float* w1i = (const float*)d_in[4];
    float* out = (float*)d_out;

    cudaFuncSetAttribute(k_mid, cudaFuncAttributeMaxDynamicSharedMemorySize, K2_SMEM);

    k_basis<<<512, 256>>>();
    dim3 g1(4, 64, 2);
    k_dft<<<g1, 128>>>(q, k);
    k_mid<<<512, 256, K2_SMEM>>>(w1r, w1i);
    dim3 g3(16, 256);
    k_irfft<<<g3, 128>>>(out);
}